// round 15
// baseline (speedup 1.0000x reference)
#include <cuda_runtime.h>
#include <cstdint>

// SMPL forward kinematics, algebraically reduced:
//   out[b,0]   = 0
//   out[b,c,m] = out[b,par(c),m] + sum_l R[b,par(c)][m][l] * v_c[l]
// where v_c = (off[c,1], off[c,2], off[c,0]) -- the G-permutations cancel.
//
// FINAL (R12 structure, best measured kernel 23.3us / DRAM 68%):
//  - TB=32 bodies per warp-tile, 4 warps/SM (one 128-thr block, 200.7 KB smem)
//  - compact stride-49 smem layout: 48 live float4/body; dead leaf-matrix
//    entries {9,10,18,19,52,53} (incl. 2 fully-dead DRAM sectors) never loaded
//  - split A/B cp.async groups interleaved with the two FK halves
//    (issue A_{t+1}; wait A_t; runs0-3; issue B_{t+1}; wait B_t; runs4-7)
//  - double buffer, warp-autonomous (no __syncthreads)
//  - windowed LDS reads: 46 LDS.128/body, matrices at compile-time offsets
//  - output staged at stride 19 (conflict-free), then streamed out fully
//    coalesced (18 STG.128 per warp covering 9216 contiguous bytes)

#define TB 32                       // bodies per tile
#define STRIDE 49                   // compact float4 per body (48 live + 1 pad)
#define BUFQ (TB * STRIDE)          // 1568 float4 per buffer
#define WPB 4                       // warps per block

static __device__ __forceinline__ void cp16(void* smem_dst, const void* gsrc) {
    unsigned s = (unsigned)__cvta_generic_to_shared(smem_dst);
    asm volatile("cp.async.cg.shared.global [%0], [%1], 16;\n" :: "r"(s), "l"(gsrc));
}

// Child c of parent p; matrix at local float offset o within run array f.
#define CHF(c, p, o, vx, vy, vz) do {                                             \
    px[c] = fmaf(f[(o)+2],(vz), fmaf(f[(o)+1],(vy), fmaf(f[(o)+0],(vx), px[p]))); \
    py[c] = fmaf(f[(o)+5],(vz), fmaf(f[(o)+4],(vy), fmaf(f[(o)+3],(vx), py[p]))); \
    pz[c] = fmaf(f[(o)+8],(vz), fmaf(f[(o)+7],(vy), fmaf(f[(o)+6],(vx), pz[p]))); \
} while(0)

// Load a run of N float4 entries starting at compact entry `base`.
#define RUN(N, base)                                                    \
    float4 q[N];                                                        \
    _Pragma("unroll")                                                   \
    for (int i = 0; i < (N); i++) q[i] = my[(base) + i];                \
    const float* f = (const float*)q;

// Stage 4 joints (j..j+3) = 3 float4 at staging slots k0..k0+2
#define ST4(k0, j) do {                                                        \
    stg[(k0)+0] = make_float4(px[(j)+0], py[(j)+0], pz[(j)+0], px[(j)+1]);     \
    stg[(k0)+1] = make_float4(py[(j)+1], pz[(j)+1], px[(j)+2], py[(j)+2]);     \
    stg[(k0)+2] = make_float4(pz[(j)+2], px[(j)+3], py[(j)+3], pz[(j)+3]);     \
} while(0)

__global__ void __launch_bounds__(128, 1)
smpl_fk_kernel(const float4* __restrict__ in4, float4* __restrict__ out4, int nb) {
    extern __shared__ float4 sm[];
    const int lane = threadIdx.x & 31;
    const int warp = threadIdx.x >> 5;
    float4* const buf0 = sm + warp * (2 * BUFQ);
    float4* const buf1 = buf0 + BUFQ;

    const int nT = (nb + TB - 1) / TB;
    const int ws = gridDim.x * WPB;
    int t = blockIdx.x * WPB + warp;
    if (t >= nT) return;

    // Compact entry map (dead orig entries 9,10,18,19,52,53):
    //   compact 0-8 <- orig 0-8 ; 9-15 <- orig 11-17 ; 16-31 <- orig 20-35 ;
    //   compact 32-47 <- orig 36-51.
    const int e1 = (lane < 9) ? lane : ((lane < 16) ? lane + 2 : lane + 4);
    // Merged second-half op: lanes 0-15 serve body bl, lanes 16-31 body bl+1.
    const int half = lane >> 4;                 // 0 or 1
    const int l16  = lane & 15;
    const int g2   = half * 54 + 36 + l16;      // gmem float4 offset within pair
    const int s2   = half * STRIDE + 32 + l16;  // smem float4 offset within pair

    // Group A: compact entries 0-31 of every body (one cp16 per body).
    auto load_A = [&](int tt, float4* buf) {
        const long long b0 = (long long)tt * TB;
        const float4* src = in4 + b0 * 54;
        const int nbl = (int)min((long long)TB, (long long)nb - b0);
        if (nbl == TB) {
            #pragma unroll
            for (int bl = 0; bl < TB; bl++)
                cp16(&buf[bl * STRIDE + lane], &src[bl * 54 + e1]);
        } else {
            for (int bl = 0; bl < nbl; bl++)
                cp16(&buf[bl * STRIDE + lane], &src[bl * 54 + e1]);
        }
        asm volatile("cp.async.commit_group;\n" ::: "memory");
    };
    // Group B: compact entries 32-47, merged body pairs.
    auto load_B = [&](int tt, float4* buf) {
        const long long b0 = (long long)tt * TB;
        const float4* src = in4 + b0 * 54;
        const int nbl = (int)min((long long)TB, (long long)nb - b0);
        if (nbl == TB) {
            #pragma unroll
            for (int bl = 0; bl < TB; bl += 2)
                cp16(&buf[bl * STRIDE + s2], &src[bl * 54 + g2]);
        } else {
            for (int bl = 0; bl < nbl; bl += 2)
                if (bl + half < nbl)
                    cp16(&buf[bl * STRIDE + s2], &src[bl * 54 + g2]);
        }
        asm volatile("cp.async.commit_group;\n" ::: "memory");
    };

    // prologue
    load_A(t, buf0);
    load_B(t, buf0);
    int cur = 0;

    while (true) {
        const int tn = t + ws;
        float4* const cbuf = cur ? buf1 : buf0;
        float4* const nbuf = cur ? buf0 : buf1;
        const bool pre = (tn < nT);

        if (pre) {
            load_A(tn, nbuf);                       // queue: [A_t,B_t,A']
            asm volatile("cp.async.wait_group 2;\n" ::: "memory");  // A_t done
        } else {
            asm volatile("cp.async.wait_group 1;\n" ::: "memory");  // A_t done
        }
        __syncwarp();

        const long long b0 = (long long)t * TB;
        const int nbl = (int)min((long long)TB, (long long)nb - b0);
        const bool active = (lane < nbl);
        const float4* my = cbuf + lane * STRIDE;
        float px[24], py[24], pz[24];

        if (active) {
            px[0] = 0.f; py[0] = 0.f; pz[0] = 0.f;
            {   // run0: entries 0-8 -> joints 0,1,2,3
                RUN(9, 0);
                CHF(1, 0, 0,   0.0372f, -0.0522f, -0.0112f);
                CHF(5, 0, 0,  -0.0383f, -0.0575f, -0.0086f);
                CHF(9, 0, 0,   0.0028f,  0.0790f, -0.0244f);
                CHF(2, 1, 9,   0.0276f, -0.2453f,  0.0051f);
                CHF(3, 2, 18, -0.0094f, -0.2710f, -0.0238f);
                CHF(4, 3, 27,  0.0261f, -0.0383f,  0.0775f);
            }
            {   // run1: entries 9-15 -> joints 5,6,7
                RUN(7, 9);
                CHF(6, 5, 1,  -0.0275f, -0.2436f, -0.0031f);
                CHF(7, 6, 10,  0.0121f, -0.2666f, -0.0219f);
                CHF(8, 7, 19, -0.0221f, -0.0394f,  0.0827f);
            }
            {   // run2: entries 16-22 -> joints 9,10,11
                RUN(7, 16);
                CHF(10, 9,  1,  0.0028f,  0.0876f,  0.0170f);
                CHF(11, 10, 10, -0.0014f,  0.0356f,  0.0018f);
                CHF(12, 11, 19, -0.0085f,  0.1343f, -0.0212f);
                CHF(14, 11, 19,  0.0455f,  0.0724f, -0.0120f);
                CHF(19, 11, 19, -0.0527f,  0.0714f, -0.0150f);
            }
            {   // run3: entries 23-25 -> joint 12
                RUN(3, 23);
                CHF(13, 12, 0,  0.0064f,  0.0565f,  0.0320f);
            }
        }

        // Issue next tile's group B, then wait for this tile's group B.
        if (pre) {
            load_B(tn, nbuf);                       // queue: [B_t,A',B']
            asm volatile("cp.async.wait_group 2;\n" ::: "memory");  // B_t done
        } else {
            asm volatile("cp.async.wait_group 0;\n" ::: "memory");
        }
        __syncwarp();

        if (active) {
            {   // run4: entries 27-31 -> joints 14,15
                RUN(5, 27);
                CHF(15, 14, 2,  0.0780f,  0.0287f, -0.0121f);
                CHF(16, 15, 11, 0.1621f, -0.0099f, -0.0146f);
            }
            {   // run5: entries 32-36 -> joints 16,17
                RUN(5, 32);
                CHF(17, 16, 0,  0.1687f,  0.0081f, -0.0047f);
                CHF(18, 17, 9,  0.0550f, -0.0068f, -0.0099f);
            }
            {   // run6: entries 38-40 -> joint 19
                RUN(3, 38);
                CHF(20, 19, 3, -0.0719f,  0.0297f, -0.0054f);
            }
            {   // run7: entries 41-47 -> joints 20,21,22
                RUN(7, 41);
                CHF(21, 20, 0,  -0.1651f, -0.0091f, -0.0198f);
                CHF(22, 21, 9,  -0.1708f,  0.0043f, -0.0038f);
                CHF(23, 22, 18, -0.0563f, -0.0055f, -0.0064f);
            }

            __syncwarp();                   // compute reads of cbuf done
            float4* stg = cbuf + lane * 19; // stage at stride 19 (conflict-free)
            ST4(0,  0);  ST4(3,  4);  ST4(6,  8);
            ST4(9,  12); ST4(12, 16); ST4(15, 20);
        } else {
            __syncwarp();
        }
        __syncwarp();

        // ---- fully coalesced store stream: nbl*18 contiguous float4 ----
        float4* dstw = out4 + b0 * 18;
        const int lim = nbl * 18;           // <= 576
        #pragma unroll
        for (int k = 0; k < 18; k++) {
            int idx = k * 32 + lane;
            int bl  = idx / 18;
            int e   = idx - bl * 18;
            if (idx < lim) dstw[idx] = cbuf[bl * 19 + e];
        }
        __syncwarp();                       // stream reads done before cbuf reused

        if (!pre) break;
        t = tn;
        cur ^= 1;
    }
}

extern "C" void kernel_launch(void* const* d_in, const int* in_sizes, int n_in,
                              void* d_out, int out_size) {
    const float4* in4 = (const float4*)d_in[0];   // orientations [B,24,3,3] f32
    float4* out4 = (float4*)d_out;                // [B,24,3] f32
    const int nb = in_sizes[0] / 216;             // B
    const int smem = WPB * 2 * BUFQ * 16;         // 200,704 B (1 block/SM)
    cudaFuncSetAttribute(smpl_fk_kernel, cudaFuncAttributeMaxDynamicSharedMemorySize, smem);
    const int nT = (nb + TB - 1) / TB;
    int blocks = 148;                              // 1 per SM
    const int maxb = (nT + WPB - 1) / WPB;
    if (blocks > maxb) blocks = maxb;
    if (blocks < 1) blocks = 1;
    smpl_fk_kernel<<<blocks, 128, smem>>>(in4, out4, nb);
}

// round 16
// speedup vs baseline: 1.0790x; 1.0790x over previous
#include <cuda_runtime.h>
#include <cstdint>

// SMPL forward kinematics, algebraically reduced:
//   out[b,0]   = 0
//   out[b,c,m] = out[b,par(c),m] + sum_l R[b,par(c)][m][l] * v_c[l]
// where v_c = (off[c,1], off[c,2], off[c,0]) -- the G-permutations cancel.
//
// FINAL (R12 structure; best measured kernel 23.3us, distribution 23.3-24.8):
//  - TB=32 bodies per warp-tile, 4 warps/SM (one 128-thr block, 200.7 KB smem)
//  - compact stride-49 smem layout: 48 live float4/body; dead leaf-matrix
//    entries {9,10,18,19,52,53} (incl. 2 fully-dead DRAM sectors) never loaded
//  - split A/B cp.async groups interleaved with the two FK halves
//    (issue A_{t+1}; wait A_t; runs0-3; issue B_{t+1}; wait B_t; runs4-7)
//  - double buffer, warp-autonomous (no __syncthreads)
//  - windowed LDS reads: 46 LDS.128/body, matrices at compile-time offsets
//  - output staged at stride 19 (conflict-free), then streamed out fully
//    coalesced (18 STG.128 per warp covering 9216 contiguous bytes)

#define TB 32                       // bodies per tile
#define STRIDE 49                   // compact float4 per body (48 live + 1 pad)
#define BUFQ (TB * STRIDE)          // 1568 float4 per buffer
#define WPB 4                       // warps per block

static __device__ __forceinline__ void cp16(void* smem_dst, const void* gsrc) {
    unsigned s = (unsigned)__cvta_generic_to_shared(smem_dst);
    asm volatile("cp.async.cg.shared.global [%0], [%1], 16;\n" :: "r"(s), "l"(gsrc));
}

// Child c of parent p; matrix at local float offset o within run array f.
#define CHF(c, p, o, vx, vy, vz) do {                                             \
    px[c] = fmaf(f[(o)+2],(vz), fmaf(f[(o)+1],(vy), fmaf(f[(o)+0],(vx), px[p]))); \
    py[c] = fmaf(f[(o)+5],(vz), fmaf(f[(o)+4],(vy), fmaf(f[(o)+3],(vx), py[p]))); \
    pz[c] = fmaf(f[(o)+8],(vz), fmaf(f[(o)+7],(vy), fmaf(f[(o)+6],(vx), pz[p]))); \
} while(0)

// Load a run of N float4 entries starting at compact entry `base`.
#define RUN(N, base)                                                    \
    float4 q[N];                                                        \
    _Pragma("unroll")                                                   \
    for (int i = 0; i < (N); i++) q[i] = my[(base) + i];                \
    const float* f = (const float*)q;

// Stage 4 joints (j..j+3) = 3 float4 at staging slots k0..k0+2
#define ST4(k0, j) do {                                                        \
    stg[(k0)+0] = make_float4(px[(j)+0], py[(j)+0], pz[(j)+0], px[(j)+1]);     \
    stg[(k0)+1] = make_float4(py[(j)+1], pz[(j)+1], px[(j)+2], py[(j)+2]);     \
    stg[(k0)+2] = make_float4(pz[(j)+2], px[(j)+3], py[(j)+3], pz[(j)+3]);     \
} while(0)

__global__ void __launch_bounds__(128, 1)
smpl_fk_kernel(const float4* __restrict__ in4, float4* __restrict__ out4, int nb) {
    extern __shared__ float4 sm[];
    const int lane = threadIdx.x & 31;
    const int warp = threadIdx.x >> 5;
    float4* const buf0 = sm + warp * (2 * BUFQ);
    float4* const buf1 = buf0 + BUFQ;

    const int nT = (nb + TB - 1) / TB;
    const int ws = gridDim.x * WPB;
    int t = blockIdx.x * WPB + warp;
    if (t >= nT) return;

    // Compact entry map (dead orig entries 9,10,18,19,52,53):
    //   compact 0-8 <- orig 0-8 ; 9-15 <- orig 11-17 ; 16-31 <- orig 20-35 ;
    //   compact 32-47 <- orig 36-51.
    const int e1 = (lane < 9) ? lane : ((lane < 16) ? lane + 2 : lane + 4);
    // Merged second-half op: lanes 0-15 serve body bl, lanes 16-31 body bl+1.
    const int half = lane >> 4;                 // 0 or 1
    const int l16  = lane & 15;
    const int g2   = half * 54 + 36 + l16;      // gmem float4 offset within pair
    const int s2   = half * STRIDE + 32 + l16;  // smem float4 offset within pair

    // Group A: compact entries 0-31 of every body (one cp16 per body).
    auto load_A = [&](int tt, float4* buf) {
        const long long b0 = (long long)tt * TB;
        const float4* src = in4 + b0 * 54;
        const int nbl = (int)min((long long)TB, (long long)nb - b0);
        if (nbl == TB) {
            #pragma unroll
            for (int bl = 0; bl < TB; bl++)
                cp16(&buf[bl * STRIDE + lane], &src[bl * 54 + e1]);
        } else {
            for (int bl = 0; bl < nbl; bl++)
                cp16(&buf[bl * STRIDE + lane], &src[bl * 54 + e1]);
        }
        asm volatile("cp.async.commit_group;\n" ::: "memory");
    };
    // Group B: compact entries 32-47, merged body pairs.
    auto load_B = [&](int tt, float4* buf) {
        const long long b0 = (long long)tt * TB;
        const float4* src = in4 + b0 * 54;
        const int nbl = (int)min((long long)TB, (long long)nb - b0);
        if (nbl == TB) {
            #pragma unroll
            for (int bl = 0; bl < TB; bl += 2)
                cp16(&buf[bl * STRIDE + s2], &src[bl * 54 + g2]);
        } else {
            for (int bl = 0; bl < nbl; bl += 2)
                if (bl + half < nbl)
                    cp16(&buf[bl * STRIDE + s2], &src[bl * 54 + g2]);
        }
        asm volatile("cp.async.commit_group;\n" ::: "memory");
    };

    // prologue
    load_A(t, buf0);
    load_B(t, buf0);
    int cur = 0;

    while (true) {
        const int tn = t + ws;
        float4* const cbuf = cur ? buf1 : buf0;
        float4* const nbuf = cur ? buf0 : buf1;
        const bool pre = (tn < nT);

        if (pre) {
            load_A(tn, nbuf);                       // queue: [A_t,B_t,A']
            asm volatile("cp.async.wait_group 2;\n" ::: "memory");  // A_t done
        } else {
            asm volatile("cp.async.wait_group 1;\n" ::: "memory");  // A_t done
        }
        __syncwarp();

        const long long b0 = (long long)t * TB;
        const int nbl = (int)min((long long)TB, (long long)nb - b0);
        const bool active = (lane < nbl);
        const float4* my = cbuf + lane * STRIDE;
        float px[24], py[24], pz[24];

        if (active) {
            px[0] = 0.f; py[0] = 0.f; pz[0] = 0.f;
            {   // run0: entries 0-8 -> joints 0,1,2,3
                RUN(9, 0);
                CHF(1, 0, 0,   0.0372f, -0.0522f, -0.0112f);
                CHF(5, 0, 0,  -0.0383f, -0.0575f, -0.0086f);
                CHF(9, 0, 0,   0.0028f,  0.0790f, -0.0244f);
                CHF(2, 1, 9,   0.0276f, -0.2453f,  0.0051f);
                CHF(3, 2, 18, -0.0094f, -0.2710f, -0.0238f);
                CHF(4, 3, 27,  0.0261f, -0.0383f,  0.0775f);
            }
            {   // run1: entries 9-15 -> joints 5,6,7
                RUN(7, 9);
                CHF(6, 5, 1,  -0.0275f, -0.2436f, -0.0031f);
                CHF(7, 6, 10,  0.0121f, -0.2666f, -0.0219f);
                CHF(8, 7, 19, -0.0221f, -0.0394f,  0.0827f);
            }
            {   // run2: entries 16-22 -> joints 9,10,11
                RUN(7, 16);
                CHF(10, 9,  1,  0.0028f,  0.0876f,  0.0170f);
                CHF(11, 10, 10, -0.0014f,  0.0356f,  0.0018f);
                CHF(12, 11, 19, -0.0085f,  0.1343f, -0.0212f);
                CHF(14, 11, 19,  0.0455f,  0.0724f, -0.0120f);
                CHF(19, 11, 19, -0.0527f,  0.0714f, -0.0150f);
            }
            {   // run3: entries 23-25 -> joint 12
                RUN(3, 23);
                CHF(13, 12, 0,  0.0064f,  0.0565f,  0.0320f);
            }
        }

        // Issue next tile's group B, then wait for this tile's group B.
        if (pre) {
            load_B(tn, nbuf);                       // queue: [B_t,A',B']
            asm volatile("cp.async.wait_group 2;\n" ::: "memory");  // B_t done
        } else {
            asm volatile("cp.async.wait_group 0;\n" ::: "memory");
        }
        __syncwarp();

        if (active) {
            {   // run4: entries 27-31 -> joints 14,15
                RUN(5, 27);
                CHF(15, 14, 2,  0.0780f,  0.0287f, -0.0121f);
                CHF(16, 15, 11, 0.1621f, -0.0099f, -0.0146f);
            }
            {   // run5: entries 32-36 -> joints 16,17
                RUN(5, 32);
                CHF(17, 16, 0,  0.1687f,  0.0081f, -0.0047f);
                CHF(18, 17, 9,  0.0550f, -0.0068f, -0.0099f);
            }
            {   // run6: entries 38-40 -> joint 19
                RUN(3, 38);
                CHF(20, 19, 3, -0.0719f,  0.0297f, -0.0054f);
            }
            {   // run7: entries 41-47 -> joints 20,21,22
                RUN(7, 41);
                CHF(21, 20, 0,  -0.1651f, -0.0091f, -0.0198f);
                CHF(22, 21, 9,  -0.1708f,  0.0043f, -0.0038f);
                CHF(23, 22, 18, -0.0563f, -0.0055f, -0.0064f);
            }

            __syncwarp();                   // compute reads of cbuf done
            float4* stg = cbuf + lane * 19; // stage at stride 19 (conflict-free)
            ST4(0,  0);  ST4(3,  4);  ST4(6,  8);
            ST4(9,  12); ST4(12, 16); ST4(15, 20);
        } else {
            __syncwarp();
        }
        __syncwarp();

        // ---- fully coalesced store stream: nbl*18 contiguous float4 ----
        float4* dstw = out4 + b0 * 18;
        const int lim = nbl * 18;           // <= 576
        #pragma unroll
        for (int k = 0; k < 18; k++) {
            int idx = k * 32 + lane;
            int bl  = idx / 18;
            int e   = idx - bl * 18;
            if (idx < lim) dstw[idx] = cbuf[bl * 19 + e];
        }
        __syncwarp();                       // stream reads done before cbuf reused

        if (!pre) break;
        t = tn;
        cur ^= 1;
    }
}

extern "C" void kernel_launch(void* const* d_in, const int* in_sizes, int n_in,
                              void* d_out, int out_size) {
    const float4* in4 = (const float4*)d_in[0];   // orientations [B,24,3,3] f32
    float4* out4 = (float4*)d_out;                // [B,24,3] f32
    const int nb = in_sizes[0] / 216;             // B
    const int smem = WPB * 2 * BUFQ * 16;         // 200,704 B (1 block/SM)
    cudaFuncSetAttribute(smpl_fk_kernel, cudaFuncAttributeMaxDynamicSharedMemorySize, smem);
    const int nT = (nb + TB - 1) / TB;
    int blocks = 148;                              // 1 per SM
    const int maxb = (nT + WPB - 1) / WPB;
    if (blocks > maxb) blocks = maxb;
    if (blocks < 1) blocks = 1;
    smpl_fk_kernel<<<blocks, 128, smem>>>(in4, out4, nb);
}